// round 3
// baseline (speedup 1.0000x reference)
#include <cuda_runtime.h>
#include <cstdint>

#define B_ 32
#define L_ 2048
#define C_ 64
#define O_ 64
#define S_ 8
#define KS_ 9
#define HALO 8
#define OUT_ROWS ((L_ - 1) * (S_ + 1) + 1)   // 18424
#define TILE_L 64
#define GR 128                                 // gemm rows per block
#define GEMM_SMEM ((64 * 64 * 2 + GR * 64) * sizeof(float))   // Ws+Bs+Fs = 64KB

typedef unsigned long long u64;

// Scratch (no cudaMalloc allowed): P = F@W^T, Q = F@bias, each (B*L, 64) fp32.
__device__ float g_P[(size_t)B_ * L_ * O_];
__device__ float g_Q[(size_t)B_ * L_ * O_];

__device__ __forceinline__ void fma2(u64& d, u64 a, u64 b) {
    asm("fma.rn.f32x2 %0, %1, %2, %0;" : "+l"(d) : "l"(a), "l"(b));
}
__device__ __forceinline__ float f2sum(u64 v) {
    float lo = __uint_as_float((unsigned)(v & 0xffffffffu));
    float hi = __uint_as_float((unsigned)(v >> 32));
    return lo + hi;
}

// non_pad_mask dtype: lengths >= L/2 so mask[0,0] and mask[0,1] are true.
// u8:  bytes [1,1,...]        -> b0=1, b1=1
// i32: bytes [1,0,0,0,...]    -> b0=1, b1=0
// f32: bytes [0,0,0x80,0x3f]  -> b0=0
__device__ __forceinline__ int mask_kind(const unsigned char* m) {
    unsigned char b0 = m[0], b1 = m[1];
    if (b0 == 1 && b1 != 0) return 0;
    if (b0 == 1) return 1;
    return 2;
}

// Kernel 1: P[r,o] = sum_c F[r,c]*W[o,c];  Q[r,o] = sum_c F[r,c]*bias[c,o]
// 128 rows/block, 256 threads. Thread = (o-quad, 8-row group).
// Packed f32x2 FMAs over c-pairs; LDS.128 everywhere. 16 LDS.128 : 128 FMA2 per c4.
// Uses 64KB DYNAMIC smem (static limit is 48KB).
__global__ __launch_bounds__(256) void gemm_kernel(const float* __restrict__ F,
                                                   const float* __restrict__ W,
                                                   const float* __restrict__ bias) {
    extern __shared__ __align__(16) float smem[];
    float* Ws = smem;                  // W row-major [o][c] (as given)      16KB
    float* Bs = smem + 64 * 64;        // biasT [o][c]                       16KB
    float* Fs = smem + 64 * 64 * 2;    // 128 rows of F                      32KB
    int tid = threadIdx.x;
    size_t rowBase = (size_t)blockIdx.x * GR;

    for (int i = tid; i < 1024; i += 256)
        ((float4*)Ws)[i] = ((const float4*)W)[i];
    for (int i = tid; i < 4096; i += 256) {
        int o = i >> 6, c = i & 63;
        Bs[i] = bias[c * 64 + o];
    }
    const float4* f4 = (const float4*)(F + rowBase * 64);
    for (int i = tid; i < GR * 16; i += 256)
        ((float4*)Fs)[i] = f4[i];
    __syncthreads();

    int o0 = (tid & 15) * 4;       // 4 consecutive o
    int r0 = (tid >> 4) * 8;       // 8 consecutive rows

    u64 accP[8][4], accQ[8][4];
#pragma unroll
    for (int j = 0; j < 8; j++)
#pragma unroll
        for (int oi = 0; oi < 4; oi++) { accP[j][oi] = 0ull; accQ[j][oi] = 0ull; }

#pragma unroll 4
    for (int c4 = 0; c4 < 16; c4++) {
        u64 wv[4][2], bv[4][2];
#pragma unroll
        for (int oi = 0; oi < 4; oi++) {
            ulonglong2 tw = *(const ulonglong2*)&Ws[(o0 + oi) * 64 + c4 * 4];
            wv[oi][0] = tw.x; wv[oi][1] = tw.y;
            ulonglong2 tb = *(const ulonglong2*)&Bs[(o0 + oi) * 64 + c4 * 4];
            bv[oi][0] = tb.x; bv[oi][1] = tb.y;
        }
#pragma unroll
        for (int j = 0; j < 8; j++) {
            ulonglong2 fv = *(const ulonglong2*)&Fs[(r0 + j) * 64 + c4 * 4];
#pragma unroll
            for (int oi = 0; oi < 4; oi++) {
                fma2(accP[j][oi], fv.x, wv[oi][0]);
                fma2(accP[j][oi], fv.y, wv[oi][1]);
                fma2(accQ[j][oi], fv.x, bv[oi][0]);
                fma2(accQ[j][oi], fv.y, bv[oi][1]);
            }
        }
    }

#pragma unroll
    for (int j = 0; j < 8; j++) {
        size_t r = rowBase + r0 + j;
        float4 p = make_float4(f2sum(accP[j][0]), f2sum(accP[j][1]),
                               f2sum(accP[j][2]), f2sum(accP[j][3]));
        float4 q = make_float4(f2sum(accQ[j][0]), f2sum(accQ[j][1]),
                               f2sum(accQ[j][2]), f2sum(accQ[j][3]));
        *(float4*)&g_P[r * 64 + o0] = p;
        *(float4*)&g_Q[r * 64 + o0] = q;
    }
}

// Kernel 2: windowed combination + expansion into the (B, 18424, 64) output.
// Block: one (b, 64-l tile). 256 threads: o4 = 4 consecutive o per thread, 16 l lanes.
__global__ __launch_bounds__(256) void combine_kernel(const float* __restrict__ times,
                                                      const void* __restrict__ maskp,
                                                      const float* __restrict__ usample,
                                                      float* __restrict__ out) {
    __shared__ __align__(16) float Ps[(TILE_L + HALO) * 64];
    __shared__ __align__(16) float Qs[(TILE_L + HALO) * 64];
    __shared__ float ts[TILE_L + HALO + 1];
    __shared__ unsigned char vs[TILE_L + HALO + 1];
    __shared__ float us[S_];

    int tid = threadIdx.x;
    int b = blockIdx.y;
    int tileStart = blockIdx.x * TILE_L;

    const float* gP = g_P + (size_t)b * L_ * 64;
    const float* gQ = g_Q + (size_t)b * L_ * 64;

    const int NF4 = (TILE_L + HALO) * 16;   // float4 count
    for (int i = tid; i < NF4; i += 256) {
        int rr = i >> 4;        // row within tile (0..71)
        int cc = i & 15;        // float4 within row
        int gl = tileStart - HALO + rr;
        float4 p = make_float4(0.f, 0.f, 0.f, 0.f), q = p;
        if (gl >= 0) {
            p = ((const float4*)(gP + (size_t)gl * 64))[cc];
            q = ((const float4*)(gQ + (size_t)gl * 64))[cc];
        }
        ((float4*)Ps)[i] = p;
        ((float4*)Qs)[i] = q;
    }
    if (tid < TILE_L + HALO + 1) {
        int kind = mask_kind((const unsigned char*)maskp);
        int gl = tileStart - HALO + tid;
        float t = 0.f;
        unsigned char v = 0;
        if (gl >= 0 && gl < L_) {
            int mi = b * L_ + gl;
            t = times[mi];
            bool mv;
            if (kind == 0)      mv = ((const unsigned char*)maskp)[mi] != 0;
            else if (kind == 1) mv = ((const int*)maskp)[mi] != 0;
            else                mv = ((const float*)maskp)[mi] != 0.f;
            v = mv ? 1 : 0;
        }
        ts[tid] = t;
        vs[tid] = v;
    }
    if (tid < S_) us[tid] = usample[tid];
    __syncthreads();

    int o4 = (tid & 15) * 4;
    int lsub0 = tid >> 4;

    for (int l_local = lsub0; l_local < TILE_L; l_local += 16) {
        int l = tileStart + l_local;
        float tl = ts[l_local + HALO];
        float ml = vs[l_local + HALO] ? 1.f : 0.f;

        float rx = 0, ry = 0, rz = 0, rw = 0;   // real (k=0..7)
        float sx = 0, sy = 0, sz = 0, sw = 0;   // sim base (k=1..8)
        float ux = 0, uy = 0, uz = 0, uw = 0;   // sum_lin (k=1..8)

#pragma unroll
        for (int k = 0; k < KS_; k++) {
            int si = l_local + k;
            float m = vs[si] ? ml : 0.f;
            float d = m * (tl - ts[si]);   // delta_k (0 when masked)
            const float4 p = *(const float4*)&Ps[si * 64 + o4];
            const float4 q = *(const float4*)&Qs[si * 64 + o4];
            float tx = fmaf(d, p.x, m * q.x);
            float ty = fmaf(d, p.y, m * q.y);
            float tz = fmaf(d, p.z, m * q.z);
            float tw = fmaf(d, p.w, m * q.w);
            if (k < KS_ - 1) { rx += tx; ry += ty; rz += tz; rw += tw; }
            if (k >= 1) {
                sx += tx; sy += ty; sz += tz; sw += tw;
                ux = fmaf(m, p.x, ux); uy = fmaf(m, p.y, uy);
                uz = fmaf(m, p.z, uz); uw = fmaf(m, p.w, uw);
            }
        }

        float* ob = out + ((size_t)b * OUT_ROWS + (size_t)l * 9) * 64 + o4;
        *(float4*)ob = make_float4(rx, ry, rz, rw);

        if (l < L_ - 1) {
            float udt = (ml != 0.f && vs[l_local + HALO + 1])
                            ? (ts[l_local + HALO + 1] - tl) : 0.f;
#pragma unroll
            for (int s = 0; s < S_; s++) {
                float f = udt * us[s];
                float4 v = make_float4(fmaf(f, ux, sx), fmaf(f, uy, sy),
                                       fmaf(f, uz, sz), fmaf(f, uw, sw));
                *(float4*)(ob + (s + 1) * 64) = v;
            }
        }
    }
}

extern "C" void kernel_launch(void* const* d_in, const int* in_sizes, int n_in,
                              void* d_out, int out_size) {
    const float* times    = (const float*)d_in[0];
    const float* features = (const float*)d_in[1];
    const void*  mask     = d_in[2];
    const float* usample  = (const float*)d_in[3];
    const float* W        = (const float*)d_in[4];
    const float* bias     = (const float*)d_in[5];
    float* out = (float*)d_out;

    static bool attr_set = false;
    if (!attr_set) {
        cudaFuncSetAttribute(gemm_kernel, cudaFuncAttributeMaxDynamicSharedMemorySize,
                             (int)GEMM_SMEM);
        attr_set = true;
    }

    gemm_kernel<<<(B_ * L_) / GR, 256, GEMM_SMEM>>>(features, W, bias);
    dim3 g2(L_ / TILE_L, B_);
    combine_kernel<<<g2, 256>>>(times, mask, usample, out);
}

// round 4
// speedup vs baseline: 1.9753x; 1.9753x over previous
#include <cuda_runtime.h>
#include <cstdint>

#define B_ 32
#define L_ 2048
#define S_ 8
#define KS_ 9
#define HALO 8
#define OUT_ROWS ((L_ - 1) * (S_ + 1) + 1)   // 18424
#define TILE_L 64
#define ROWS_T (TILE_L + HALO)               // 72
// dynamic smem: Wt(4096) + Bt(4096) + Fs(4608) + Ps(4608) + Qs(4608) floats
#define FUSED_SMEM ((4096 * 2 + 4608 * 3) * sizeof(float))   // 88064 B

typedef unsigned long long u64;

__device__ __forceinline__ void fma2(u64& d, u64 a, u64 b) {
    asm("fma.rn.f32x2 %0, %1, %2, %0;" : "+l"(d) : "l"(a), "l"(b));
}
__device__ __forceinline__ u64 splat2(float f) {
    u64 r;
    asm("mov.b64 %0, {%1, %1};" : "=l"(r) : "f"(f));
    return r;
}

// non_pad_mask dtype probe. lengths >= L/2 so mask[0,0], mask[0,1] are true.
// u8: [1,1,..] -> b0=1,b1=1 | i32: [1,0,0,0,..] -> b0=1,b1=0 | f32: [0,0,0x80,0x3f] -> b0=0
__device__ __forceinline__ int mask_kind(const unsigned char* m) {
    unsigned char b0 = m[0], b1 = m[1];
    if (b0 == 1 && b1 != 0) return 0;
    if (b0 == 1) return 1;
    return 2;
}

// One block = one (b, 64-l tile). Phase 1: GEMM the 72-row halo tile of F into
// Ps/Qs in shared memory (P = F@W^T, Q = F@bias) using packed f32x2 FMAs with
// only 18 u64 accumulators per thread. Phase 2: windowed combine + expansion.
__global__ __launch_bounds__(256) void fused_kernel(const float* __restrict__ times,
                                                    const float* __restrict__ F,
                                                    const void* __restrict__ maskp,
                                                    const float* __restrict__ usample,
                                                    const float* __restrict__ W,
                                                    const float* __restrict__ bias,
                                                    float* __restrict__ out) {
    extern __shared__ __align__(16) float smem[];
    float* Wt = smem;               // [c][o]  (transposed from W[o][c])
    float* Bt = Wt + 4096;          // [c][o]  (bias is (C,O) row-major: copy as-is)
    float* Fs = Bt + 4096;          // 72 x 64
    float* Ps = Fs + ROWS_T * 64;   // 72 x 64
    float* Qs = Ps + ROWS_T * 64;   // 72 x 64
    __shared__ float ts[ROWS_T + 1];
    __shared__ unsigned char vs[ROWS_T + 1];
    __shared__ float us[S_];

    int tid = threadIdx.x;
    int b = blockIdx.y;
    int tileStart = blockIdx.x * TILE_L;

    // ---- load W (transpose), bias (copy), F halo tile, times/mask/usample ----
    for (int i = tid; i < 4096; i += 256) {
        int o = i >> 6, c = i & 63;
        Wt[c * 64 + o] = W[i];
    }
    for (int i = tid; i < 1024; i += 256)
        ((float4*)Bt)[i] = ((const float4*)bias)[i];

    const float* gF = F + (size_t)b * L_ * 64;
    for (int i = tid; i < ROWS_T * 16; i += 256) {
        int rr = i >> 4, cc = i & 15;
        int gl = tileStart - HALO + rr;
        float4 f = make_float4(0.f, 0.f, 0.f, 0.f);
        if (gl >= 0) f = ((const float4*)(gF + (size_t)gl * 64))[cc];
        ((float4*)Fs)[i] = f;
    }
    if (tid < ROWS_T + 1) {
        int kind = mask_kind((const unsigned char*)maskp);
        int gl = tileStart - HALO + tid;
        float t = 0.f;
        unsigned char v = 0;
        if (gl >= 0 && gl < L_) {
            int mi = b * L_ + gl;
            t = times[mi];
            bool mv;
            if (kind == 0)      mv = ((const unsigned char*)maskp)[mi] != 0;
            else if (kind == 1) mv = ((const int*)maskp)[mi] != 0;
            else                mv = ((const float*)maskp)[mi] != 0.f;
            v = mv ? 1 : 0;
        }
        ts[tid] = t;
        vs[tid] = v;
    }
    if (tid < S_) us[tid] = usample[tid];
    __syncthreads();

    // ---- phase 1: GEMM tile -> Ps/Qs.  thread = (o-pair o2, 9-row group rg) ----
    {
        int o2 = tid & 31;          // o = 2*o2, 2*o2+1  (lane id: conflict-free LDS.64)
        int rg = tid >> 5;          // warp-uniform -> Fs loads are broadcasts
        int row0 = rg * 9;

        u64 aP[9], aQ[9];
#pragma unroll
        for (int j = 0; j < 9; j++) { aP[j] = 0ull; aQ[j] = 0ull; }

#pragma unroll
        for (int c4 = 0; c4 < 16; c4++) {
            float4 fv[9];
#pragma unroll
            for (int j = 0; j < 9; j++)
                fv[j] = *(const float4*)&Fs[(row0 + j) * 64 + c4 * 4];
#pragma unroll
            for (int cc = 0; cc < 4; cc++) {
                int c = c4 * 4 + cc;
                u64 w2 = *(const u64*)&Wt[c * 64 + o2 * 2];
                u64 b2 = *(const u64*)&Bt[c * 64 + o2 * 2];
#pragma unroll
                for (int j = 0; j < 9; j++) {
                    u64 ff = splat2(((const float*)&fv[j])[cc]);
                    fma2(aP[j], ff, w2);
                    fma2(aQ[j], ff, b2);
                }
            }
        }
#pragma unroll
        for (int j = 0; j < 9; j++) {
            *(u64*)&Ps[(row0 + j) * 64 + o2 * 2] = aP[j];
            *(u64*)&Qs[(row0 + j) * 64 + o2 * 2] = aQ[j];
        }
    }
    __syncthreads();

    // ---- phase 2: windowed combine + expansion ----
    int o4 = (tid & 15) * 4;
    int lsub0 = tid >> 4;

    for (int l_local = lsub0; l_local < TILE_L; l_local += 16) {
        int l = tileStart + l_local;
        float tl = ts[l_local + HALO];
        float ml = vs[l_local + HALO] ? 1.f : 0.f;

        float rx = 0, ry = 0, rz = 0, rw = 0;   // real (k=0..7)
        float sx = 0, sy = 0, sz = 0, sw = 0;   // sim base (k=1..8)
        float ux = 0, uy = 0, uz = 0, uw = 0;   // sum_lin (k=1..8)

#pragma unroll
        for (int k = 0; k < KS_; k++) {
            int si = l_local + k;
            float m = vs[si] ? ml : 0.f;
            float d = m * (tl - ts[si]);
            const float4 p = *(const float4*)&Ps[si * 64 + o4];
            const float4 q = *(const float4*)&Qs[si * 64 + o4];
            float tx = fmaf(d, p.x, m * q.x);
            float ty = fmaf(d, p.y, m * q.y);
            float tz = fmaf(d, p.z, m * q.z);
            float tw = fmaf(d, p.w, m * q.w);
            if (k < KS_ - 1) { rx += tx; ry += ty; rz += tz; rw += tw; }
            if (k >= 1) {
                sx += tx; sy += ty; sz += tz; sw += tw;
                ux = fmaf(m, p.x, ux); uy = fmaf(m, p.y, uy);
                uz = fmaf(m, p.z, uz); uw = fmaf(m, p.w, uw);
            }
        }

        float* ob = out + ((size_t)b * OUT_ROWS + (size_t)l * 9) * 64 + o4;
        *(float4*)ob = make_float4(rx, ry, rz, rw);

        if (l < L_ - 1) {
            float udt = (ml != 0.f && vs[l_local + HALO + 1])
                            ? (ts[l_local + HALO + 1] - tl) : 0.f;
#pragma unroll
            for (int s = 0; s < S_; s++) {
                float f = udt * us[s];
                float4 v = make_float4(fmaf(f, ux, sx), fmaf(f, uy, sy),
                                       fmaf(f, uz, sz), fmaf(f, uw, sw));
                *(float4*)(ob + (s + 1) * 64) = v;
            }
        }
    }
}

extern "C" void kernel_launch(void* const* d_in, const int* in_sizes, int n_in,
                              void* d_out, int out_size) {
    const float* times    = (const float*)d_in[0];
    const float* features = (const float*)d_in[1];
    const void*  mask     = d_in[2];
    const float* usample  = (const float*)d_in[3];
    const float* W        = (const float*)d_in[4];
    const float* bias     = (const float*)d_in[5];
    float* out = (float*)d_out;

    cudaFuncSetAttribute(fused_kernel, cudaFuncAttributeMaxDynamicSharedMemorySize,
                         (int)FUSED_SMEM);
    dim3 g(L_ / TILE_L, B_);
    fused_kernel<<<g, 256, FUSED_SMEM>>>(times, features, mask, usample, W, bias, out);
}

// round 5
// speedup vs baseline: 2.3208x; 1.1749x over previous
#include <cuda_runtime.h>
#include <cstdint>

#define B_ 32
#define L_ 2048
#define S_ 8
#define KS_ 9
#define HALO 8
#define OUT_ROWS ((L_ - 1) * (S_ + 1) + 1)   // 18424
#define TILE_L 64
#define ROWS_T (TILE_L + HALO)               // 72
#define WT_STRIDE 66                          // padded: kills 32-way STS conflicts

// region A (phase 1): Wt[66*64] + Bt[64*64] + Fs[72*64] = 12928 floats
// region B (phase 2): Ps[72*64] + Qs[72*64] = 9216 floats, ALIASED over region A
#define SMEM_FLOATS (WT_STRIDE * 64 + 64 * 64 + ROWS_T * 64)
#define FUSED_SMEM (SMEM_FLOATS * sizeof(float))   // 51712 B -> 3-4 blocks/SM

typedef unsigned long long u64;

__device__ __forceinline__ void fma2(u64& d, u64 a, u64 b) {
    asm("fma.rn.f32x2 %0, %1, %2, %0;" : "+l"(d) : "l"(a), "l"(b));
}
__device__ __forceinline__ u64 splat2(float f) {
    u64 r;
    asm("mov.b64 %0, {%1, %1};" : "=l"(r) : "f"(f));
    return r;
}

// non_pad_mask dtype probe. lengths >= L/2 so mask[0,0], mask[0,1] are true.
// u8: [1,1,..] | i32: [1,0,0,0,..] | f32: [0,0,0x80,0x3f]
__device__ __forceinline__ int mask_kind(const unsigned char* m) {
    unsigned char b0 = m[0], b1 = m[1];
    if (b0 == 1 && b1 != 0) return 0;
    if (b0 == 1) return 1;
    return 2;
}

__global__ __launch_bounds__(256, 3) void fused_kernel(const float* __restrict__ times,
                                                       const float* __restrict__ F,
                                                       const void* __restrict__ maskp,
                                                       const float* __restrict__ usample,
                                                       const float* __restrict__ W,
                                                       const float* __restrict__ bias,
                                                       float* __restrict__ out) {
    extern __shared__ __align__(16) float smem[];
    float* Wt = smem;                          // [c][o], row stride 66
    float* Bt = smem + WT_STRIDE * 64;         // [c][o], stride 64
    float* Fs = Bt + 64 * 64;                  // 72 x 64
    // phase-2 aliases (valid only after the post-GEMM sync):
    float* Ps = smem;                          // 72 x 64
    float* Qs = smem + ROWS_T * 64;            // 72 x 64
    __shared__ float ts[ROWS_T + 1];
    __shared__ unsigned char vs[ROWS_T + 1];
    __shared__ float us[S_];

    int tid = threadIdx.x;
    int b = blockIdx.y;
    int tileStart = blockIdx.x * TILE_L;

    // ---- loads: W (transpose, padded), bias (copy), F halo tile, scalars ----
    for (int i = tid; i < 4096; i += 256) {
        int o = i >> 6, c = i & 63;
        Wt[c * WT_STRIDE + o] = W[i];
    }
    for (int i = tid; i < 1024; i += 256) {
        int o4 = (i & 15) * 4, c = i >> 4;
        *(float4*)&Bt[c * 64 + o4] = ((const float4*)bias)[i];
    }
    const float* gF = F + (size_t)b * L_ * 64;
    for (int i = tid; i < ROWS_T * 16; i += 256) {
        int rr = i >> 4, cc = i & 15;
        int gl = tileStart - HALO + rr;
        float4 f = make_float4(0.f, 0.f, 0.f, 0.f);
        if (gl >= 0) f = ((const float4*)(gF + (size_t)gl * 64))[cc];
        ((float4*)Fs)[i] = f;
    }
    if (tid < ROWS_T + 1) {
        int kind = mask_kind((const unsigned char*)maskp);
        int gl = tileStart - HALO + tid;
        float t = 0.f;
        unsigned char v = 0;
        if (gl >= 0 && gl < L_) {
            int mi = b * L_ + gl;
            t = times[mi];
            bool mv;
            if (kind == 0)      mv = ((const unsigned char*)maskp)[mi] != 0;
            else if (kind == 1) mv = ((const int*)maskp)[mi] != 0;
            else                mv = ((const float*)maskp)[mi] != 0.f;
            v = mv ? 1 : 0;
        }
        ts[tid] = t;
        vs[tid] = v;
    }
    if (tid < S_) us[tid] = usample[tid];
    __syncthreads();

    // ---- phase 1: GEMM tile into registers. thread = (o-pair o2, 9-row group rg) ----
    int o2 = tid & 31;          // o = 2*o2, 2*o2+1
    int rg = tid >> 5;          // warp-uniform -> Fs loads broadcast
    int row0 = rg * 9;

    u64 aP[9], aQ[9];
#pragma unroll
    for (int j = 0; j < 9; j++) { aP[j] = 0ull; aQ[j] = 0ull; }

#pragma unroll
    for (int c4 = 0; c4 < 16; c4++) {
        float4 fv[9];
#pragma unroll
        for (int j = 0; j < 9; j++)
            fv[j] = *(const float4*)&Fs[(row0 + j) * 64 + c4 * 4];
#pragma unroll
        for (int cc = 0; cc < 4; cc++) {
            int c = c4 * 4 + cc;
            u64 w2 = *(const u64*)&Wt[c * WT_STRIDE + o2 * 2];
            u64 b2 = *(const u64*)&Bt[c * 64 + o2 * 2];
#pragma unroll
            for (int j = 0; j < 9; j++) {
                u64 ff = splat2(((const float*)&fv[j])[cc]);
                fma2(aP[j], ff, w2);
                fma2(aQ[j], ff, b2);
            }
        }
    }
    __syncthreads();   // all Wt/Bt/Fs reads complete -> safe to overwrite (alias)

#pragma unroll
    for (int j = 0; j < 9; j++) {
        *(u64*)&Ps[(row0 + j) * 64 + o2 * 2] = aP[j];
        *(u64*)&Qs[(row0 + j) * 64 + o2 * 2] = aQ[j];
    }
    __syncthreads();

    // ---- phase 2: windowed combine + expansion ----
    int o4 = (tid & 15) * 4;
    int lsub0 = tid >> 4;

    for (int l_local = lsub0; l_local < TILE_L; l_local += 16) {
        int l = tileStart + l_local;
        float tl = ts[l_local + HALO];
        float ml = vs[l_local + HALO] ? 1.f : 0.f;

        float rx = 0, ry = 0, rz = 0, rw = 0;   // real (k=0..7)
        float sx = 0, sy = 0, sz = 0, sw = 0;   // sim base (k=1..8)
        float ux = 0, uy = 0, uz = 0, uw = 0;   // sum_lin (k=1..8)

#pragma unroll
        for (int k = 0; k < KS_; k++) {
            int si = l_local + k;
            float m = vs[si] ? ml : 0.f;
            float d = m * (tl - ts[si]);
            const float4 p = *(const float4*)&Ps[si * 64 + o4];
            const float4 q = *(const float4*)&Qs[si * 64 + o4];
            float tx = fmaf(d, p.x, m * q.x);
            float ty = fmaf(d, p.y, m * q.y);
            float tz = fmaf(d, p.z, m * q.z);
            float tw = fmaf(d, p.w, m * q.w);
            if (k < KS_ - 1) { rx += tx; ry += ty; rz += tz; rw += tw; }
            if (k >= 1) {
                sx += tx; sy += ty; sz += tz; sw += tw;
                ux = fmaf(m, p.x, ux); uy = fmaf(m, p.y, uy);
                uz = fmaf(m, p.z, uz); uw = fmaf(m, p.w, uw);
            }
        }

        float* ob = out + ((size_t)b * OUT_ROWS + (size_t)l * 9) * 64 + o4;
        *(float4*)ob = make_float4(rx, ry, rz, rw);

        if (l < L_ - 1) {
            float udt = (ml != 0.f && vs[l_local + HALO + 1])
                            ? (ts[l_local + HALO + 1] - tl) : 0.f;
#pragma unroll
            for (int s = 0; s < S_; s++) {
                float f = udt * us[s];
                float4 v = make_float4(fmaf(f, ux, sx), fmaf(f, uy, sy),
                                       fmaf(f, uz, sz), fmaf(f, uw, sw));
                *(float4*)(ob + (s + 1) * 64) = v;
            }
        }
    }
}

extern "C" void kernel_launch(void* const* d_in, const int* in_sizes, int n_in,
                              void* d_out, int out_size) {
    const float* times    = (const float*)d_in[0];
    const float* features = (const float*)d_in[1];
    const void*  mask     = d_in[2];
    const float* usample  = (const float*)d_in[3];
    const float* W        = (const float*)d_in[4];
    const float* bias     = (const float*)d_in[5];
    float* out = (float*)d_out;

    cudaFuncSetAttribute(fused_kernel, cudaFuncAttributeMaxDynamicSharedMemorySize,
                         (int)FUSED_SMEM);
    dim3 g(L_ / TILE_L, B_);
    fused_kernel<<<g, 256, FUSED_SMEM>>>(times, features, mask, usample, W, bias, out);
}

// round 7
// speedup vs baseline: 2.3691x; 1.0208x over previous
#include <cuda_runtime.h>
#include <cstdint>

#define B_ 32
#define L_ 2048
#define S_ 8
#define KS_ 9
#define HALO 8
#define OUT_ROWS ((L_ - 1) * (S_ + 1) + 1)   // 18424
#define TILE_L 64
#define ROWS_T (TILE_L + HALO)               // 72
#define WT_STRIDE 66                          // padded: kills 32-way STS conflicts

// region A (phase 1): Wt[66*64] + Bt[64*64] + Fs[72*64] = 12928 floats
// region B (phase 2): Ps[72*64] + Qs[72*64] = 9216 floats, ALIASED over region A
#define SMEM_FLOATS (WT_STRIDE * 64 + 64 * 64 + ROWS_T * 64)
#define FUSED_SMEM (SMEM_FLOATS * sizeof(float))   // 51712 B -> 3 blocks/SM

typedef unsigned long long u64;

__device__ __forceinline__ void fma2(u64& d, u64 a, u64 b) {
    asm("fma.rn.f32x2 %0, %1, %2, %0;" : "+l"(d) : "l"(a), "l"(b));
}
__device__ __forceinline__ u64 mul2(u64 a, u64 b) {
    u64 r;
    asm("mul.rn.f32x2 %0, %1, %2;" : "=l"(r) : "l"(a), "l"(b));
    return r;
}
__device__ __forceinline__ u64 splat2(float f) {
    u64 r;
    asm("mov.b64 %0, {%1, %1};" : "=l"(r) : "f"(f));
    return r;
}

// non_pad_mask dtype probe. lengths >= L/2 so mask[0,0], mask[0,1] are true.
// u8: [1,1,..] | i32: [1,0,0,0,..] | f32: [0,0,0x80,0x3f]
__device__ __forceinline__ int mask_kind(const unsigned char* m) {
    unsigned char b0 = m[0], b1 = m[1];
    if (b0 == 1 && b1 != 0) return 0;
    if (b0 == 1) return 1;
    return 2;
}

__global__ __launch_bounds__(256, 3) void fused_kernel(const float* __restrict__ times,
                                                       const float* __restrict__ F,
                                                       const void* __restrict__ maskp,
                                                       const float* __restrict__ usample,
                                                       const float* __restrict__ W,
                                                       const float* __restrict__ bias,
                                                       float* __restrict__ out) {
    extern __shared__ __align__(16) float smem[];
    float* Wt = smem;                          // [c][o], row stride 66
    float* Bt = smem + WT_STRIDE * 64;         // [c][o], stride 64
    float* Fs = Bt + 64 * 64;                  // 72 x 64
    // phase-2 aliases (valid only after the post-GEMM sync). Hold MASKED m_j*P, m_j*Q.
    float* Ps = smem;                          // 72 x 64
    float* Qs = smem + ROWS_T * 64;            // 72 x 64
    __shared__ float ts[ROWS_T + 1];
    __shared__ float vsf[ROWS_T + 1];          // mask as float 0/1
    __shared__ float us[S_];

    int tid = threadIdx.x;
    int b = blockIdx.y;
    int tileStart = blockIdx.x * TILE_L;

    // ---- loads: W (transpose, padded), bias (copy), F halo tile, scalars ----
    for (int i = tid; i < 4096; i += 256) {
        int o = i >> 6, c = i & 63;
        Wt[c * WT_STRIDE + o] = W[i];
    }
    for (int i = tid; i < 1024; i += 256) {
        int o4 = (i & 15) * 4, c = i >> 4;
        *(float4*)&Bt[c * 64 + o4] = ((const float4*)bias)[i];
    }
    const float* gF = F + (size_t)b * L_ * 64;
    for (int i = tid; i < ROWS_T * 16; i += 256) {
        int rr = i >> 4, cc = i & 15;
        int gl = tileStart - HALO + rr;
        float4 f = make_float4(0.f, 0.f, 0.f, 0.f);
        if (gl >= 0) f = ((const float4*)(gF + (size_t)gl * 64))[cc];
        ((float4*)Fs)[i] = f;
    }
    if (tid < ROWS_T + 1) {
        int kind = mask_kind((const unsigned char*)maskp);
        int gl = tileStart - HALO + tid;
        float t = 0.f, v = 0.f;
        if (gl >= 0 && gl < L_) {
            int mi = b * L_ + gl;
            t = times[mi];
            bool mv;
            if (kind == 0)      mv = ((const unsigned char*)maskp)[mi] != 0;
            else if (kind == 1) mv = ((const int*)maskp)[mi] != 0;
            else                mv = ((const float*)maskp)[mi] != 0.f;
            v = mv ? 1.f : 0.f;
        }
        ts[tid] = t;
        vsf[tid] = v;
    }
    if (tid < S_) us[tid] = usample[tid];
    __syncthreads();

    // ---- phase 1: GEMM tile into registers. thread = (o-pair o2, 9-row group rg) ----
    int o2 = tid & 31;          // o = 2*o2, 2*o2+1
    int rg = tid >> 5;          // warp-uniform -> Fs loads broadcast
    int row0 = rg * 9;

    u64 aP[9], aQ[9];
#pragma unroll
    for (int j = 0; j < 9; j++) { aP[j] = 0ull; aQ[j] = 0ull; }

#pragma unroll
    for (int c4 = 0; c4 < 16; c4++) {
        float4 fv[9];
#pragma unroll
        for (int j = 0; j < 9; j++)
            fv[j] = *(const float4*)&Fs[(row0 + j) * 64 + c4 * 4];
#pragma unroll
        for (int cc = 0; cc < 4; cc++) {
            int c = c4 * 4 + cc;
            u64 w2 = *(const u64*)&Wt[c * WT_STRIDE + o2 * 2];
            u64 b2 = *(const u64*)&Bt[c * 64 + o2 * 2];
#pragma unroll
            for (int j = 0; j < 9; j++) {
                u64 ff = splat2(((const float*)&fv[j])[cc]);
                fma2(aP[j], ff, w2);
                fma2(aQ[j], ff, b2);
            }
        }
    }
    __syncthreads();   // all Wt/Bt/Fs reads complete -> safe to overwrite (alias)

    // writeback with mask folded in: Ps = m_j*P, Qs = m_j*Q
#pragma unroll
    for (int j = 0; j < 9; j++) {
        u64 mm = splat2(vsf[row0 + j]);
        *(u64*)&Ps[(row0 + j) * 64 + o2 * 2] = mul2(aP[j], mm);
        *(u64*)&Qs[(row0 + j) * 64 + o2 * 2] = mul2(aQ[j], mm);
    }
    __syncthreads();

    // ---- phase 2: sliding-window combine ----
    // real[l] = m_l*(t_l*A + E),        A = sum_{j=l-8..l-1} mP_j,  E = sum (mQ_j - t_j*mP_j)
    // sim[l]  = m_l*(t_l*An + En),      An/En = window advanced to j=l-7..l  (8 taps!)
    // sum_lin = m_l*An.  Carry (An,En) into the next l.
    // thread = (o4 lane 0..15, contiguous 4-l chunk 0..15).
    {
        int o4 = (tid & 15) * 4;
        int l0 = (tid >> 4) * 4;   // local l of chunk start

        float4 A = make_float4(0.f, 0.f, 0.f, 0.f);
        float4 E = make_float4(0.f, 0.f, 0.f, 0.f);
#pragma unroll
        for (int i = 0; i < 8; i++) {          // init window j = l0-8 .. l0-1 (rows l0..l0+7)
            int r = l0 + i;
            float4 p = *(const float4*)&Ps[r * 64 + o4];
            float4 q = *(const float4*)&Qs[r * 64 + o4];
            float t = ts[r];
            A.x += p.x; A.y += p.y; A.z += p.z; A.w += p.w;
            E.x += fmaf(-t, p.x, q.x); E.y += fmaf(-t, p.y, q.y);
            E.z += fmaf(-t, p.z, q.z); E.w += fmaf(-t, p.w, q.w);
        }

#pragma unroll
        for (int i = 0; i < 4; i++) {
            int ll = l0 + i;
            int l = tileStart + ll;
            float tl = ts[ll + HALO];
            float m  = vsf[ll + HALO];

            float4 pn = *(const float4*)&Ps[(ll + HALO) * 64 + o4];   // new tap j=l
            float4 qn = *(const float4*)&Qs[(ll + HALO) * 64 + o4];
            float4 po = *(const float4*)&Ps[ll * 64 + o4];            // old tap j=l-8
            float4 qo = *(const float4*)&Qs[ll * 64 + o4];
            float to = ts[ll];

            // advanced 8-tap window j = l-7..l  (add new, drop old)
            float4 An, En;
            An.x = A.x + pn.x - po.x; An.y = A.y + pn.y - po.y;
            An.z = A.z + pn.z - po.z; An.w = A.w + pn.w - po.w;
            En.x = fmaf(to, po.x, fmaf(-tl, pn.x, E.x + qn.x) - qo.x);
            En.y = fmaf(to, po.y, fmaf(-tl, pn.y, E.y + qn.y) - qo.y);
            En.z = fmaf(to, po.z, fmaf(-tl, pn.z, E.z + qn.z) - qo.z);
            En.w = fmaf(to, po.w, fmaf(-tl, pn.w, E.w + qn.w) - qo.w);

            float4 re, sb, sl;
            re.x = m * fmaf(tl, A.x, E.x);   re.y = m * fmaf(tl, A.y, E.y);
            re.z = m * fmaf(tl, A.z, E.z);   re.w = m * fmaf(tl, A.w, E.w);
            sb.x = m * fmaf(tl, An.x, En.x); sb.y = m * fmaf(tl, An.y, En.y);
            sb.z = m * fmaf(tl, An.z, En.z); sb.w = m * fmaf(tl, An.w, En.w);
            sl.x = m * An.x; sl.y = m * An.y; sl.z = m * An.z; sl.w = m * An.w;

            float* ob = out + ((size_t)b * OUT_ROWS + (size_t)l * 9) * 64 + o4;
            *(float4*)ob = re;

            if (l < L_ - 1) {
                float udt = (m != 0.f && vsf[ll + HALO + 1] != 0.f)
                                ? (ts[ll + HALO + 1] - tl) : 0.f;
#pragma unroll
                for (int s = 0; s < S_; s++) {
                    float f = udt * us[s];
                    float4 v = make_float4(fmaf(f, sl.x, sb.x), fmaf(f, sl.y, sb.y),
                                           fmaf(f, sl.z, sb.z), fmaf(f, sl.w, sb.w));
                    *(float4*)(ob + (s + 1) * 64) = v;
                }
            }

            A = An;   // window for real[l+1] is exactly j = l-7..l
            E = En;
        }
    }
}

extern "C" void kernel_launch(void* const* d_in, const int* in_sizes, int n_in,
                              void* d_out, int out_size) {
    const float* times    = (const float*)d_in[0];
    const float* features = (const float*)d_in[1];
    const void*  mask     = d_in[2];
    const float* usample  = (const float*)d_in[3];
    const float* W        = (const float*)d_in[4];
    const float* bias     = (const float*)d_in[5];
    float* out = (float*)d_out;

    cudaFuncSetAttribute(fused_kernel, cudaFuncAttributeMaxDynamicSharedMemorySize,
                         (int)FUSED_SMEM);
    dim3 g(L_ / TILE_L, B_);
    fused_kernel<<<g, 256, FUSED_SMEM>>>(times, features, mask, usample, W, bias, out);
}